// round 1
// baseline (speedup 1.0000x reference)
#include <cuda_runtime.h>
#include <cuda_bf16.h>
#include <cstddef>

#define NN 50000
#define FF 256
#define HH 8
#define DHH 32
#define DD 16
#define RR 20
#define FHID 1024
#define HOPS 10

// ---------------- scratch (static device globals; no allocation) ----------------
__device__ float g_x[NN * FF];         // LN'd ent_feat
__device__ float g_rln[RR * FF];       // LN'd rel_feat
__device__ float g_fe[NN * FF];        // feat0 = x @ W_ent
__device__ float g_fA[NN * FF];        // ping
__device__ float g_fB[NN * FF];        // pong
__device__ float g_eh[NN * HH];
__device__ float g_et[NN * HH];
__device__ float g_er[RR * HH];
__device__ float g_Ah[FF * HH];
__device__ float g_At[FF * HH];
__device__ float g_Ar[FF * HH];
__device__ int   g_tidx[NN * HH * 8];  // compacted top-k src indices
__device__ float g_tw[NN * HH * 8];    // compacted renormalized weights
__device__ float g_rst[NN * FF];
__device__ float g_y[NN * FF];
__device__ float g_hid[(size_t)NN * FHID];

// ---------------- A[f,h] = sum_dh W[f, h*DH+dh] * attn[h,dh] ----------------
__global__ void reduce_attn_kernel(const float* __restrict__ W,
                                   const float* __restrict__ attn,
                                   float* __restrict__ A) {
    int idx = blockIdx.x * blockDim.x + threadIdx.x;
    if (idx >= FF * HH) return;
    int f = idx / HH, h = idx % HH;
    float s = 0.f;
#pragma unroll
    for (int d = 0; d < DHH; d++)
        s += W[(size_t)f * (HH * DHH) + h * DHH + d] * attn[h * DHH + d];
    A[f * HH + h] = s;
}

// ---------------- LayerNorm over F=256 (optionally add residual input first) ----------------
__global__ void ln_kernel(const float* __restrict__ X, const float* __restrict__ add,
                          const float* __restrict__ g, const float* __restrict__ b,
                          float* __restrict__ Y, float* __restrict__ rstOut, int rows) {
    int i = blockIdx.x;
    if (i >= rows) return;
    int t = threadIdx.x;                // 256 threads
    float v = X[(size_t)i * FF + t];
    if (add) v += add[(size_t)i * FF + t];
    if (rstOut) rstOut[(size_t)i * FF + t] = v;

    __shared__ float red[8];
    int lane = t & 31, wid = t >> 5;
    float s = v;
#pragma unroll
    for (int o = 16; o; o >>= 1) s += __shfl_xor_sync(0xffffffffu, s, o);
    if (lane == 0) red[wid] = s;
    __syncthreads();
    float tot = 0.f;
#pragma unroll
    for (int w = 0; w < 8; w++) tot += red[w];
    float mean = tot * (1.f / FF);
    float d = v - mean;
    __syncthreads();
    s = d * d;
#pragma unroll
    for (int o = 16; o; o >>= 1) s += __shfl_xor_sync(0xffffffffu, s, o);
    if (lane == 0) red[wid] = s;
    __syncthreads();
    tot = 0.f;
#pragma unroll
    for (int w = 0; w < 8; w++) tot += red[w];
    float var = tot * (1.f / FF);
    Y[(size_t)i * FF + t] = d * rsqrtf(var + 1e-5f) * g[t] + b[t];
}

// ---------------- per-row 8-head dot products: o1 = X@A1, o2 = X@A2 ----------------
__global__ void dot_heads_kernel(const float* __restrict__ X,
                                 const float* __restrict__ A1, const float* __restrict__ A2,
                                 float* __restrict__ o1, float* __restrict__ o2, int rows) {
    int i = blockIdx.x;
    if (i >= rows) return;
    int t = threadIdx.x;          // 256 threads; warp = head
    int h = t >> 5, lane = t & 31;
    float s1 = 0.f, s2 = 0.f;
#pragma unroll
    for (int j = 0; j < 8; j++) {
        int f = lane + 32 * j;
        float x = X[(size_t)i * FF + f];
        s1 += x * A1[f * HH + h];
        s2 += x * A2[f * HH + h];
    }
#pragma unroll
    for (int o = 16; o; o >>= 1) {
        s1 += __shfl_xor_sync(0xffffffffu, s1, o);
        s2 += __shfl_xor_sync(0xffffffffu, s2, o);
    }
    if (lane == 0) { o1[i * HH + h] = s1; o2[i * HH + h] = s2; }
}

// ---------------- edge softmax + top-5 sparsify + renormalize, compacted ----------------
__global__ void attn_topk_kernel(const float* __restrict__ eh, const float* __restrict__ et,
                                 const float* __restrict__ er,
                                 const int* __restrict__ src, const int* __restrict__ rid,
                                 int* __restrict__ tidx, float* __restrict__ tw) {
    int warp = (blockIdx.x * blockDim.x + threadIdx.x) >> 5;
    if (warp >= NN) return;
    int lane = threadIdx.x & 31;
    int d = lane & 15;                        // lanes 16..31 mirror 0..15
    int i = warp;
    int s  = src[i * DD + d];
    int rd = rid[i * DD + d];
#pragma unroll
    for (int h = 0; h < HH; h++) {
        float e = eh[s * HH + h] + et[i * HH + h] + er[rd * HH + h];
        e = e > 0.f ? e : 0.2f * e;           // LeakyReLU
        float m = e;
#pragma unroll
        for (int o = 8; o; o >>= 1) m = fmaxf(m, __shfl_xor_sync(0xffffffffu, m, o, 16));
        float a = __expf(e - m);
        float ssum = a;
#pragma unroll
        for (int o = 8; o; o >>= 1) ssum += __shfl_xor_sync(0xffffffffu, ssum, o, 16);
        a /= ssum;
        // iterative top-5 (distinct lanes; duplicate values counted like lax.top_k)
        float tmp = a, topsum = 0.f, kth = 0.f;
#pragma unroll
        for (int it = 0; it < 5; it++) {
            float mv = tmp; int ml = d;
#pragma unroll
            for (int o = 8; o; o >>= 1) {
                float ov = __shfl_xor_sync(0xffffffffu, mv, o, 16);
                int   ol = __shfl_xor_sync(0xffffffffu, ml, o, 16);
                if (ov > mv || (ov == mv && ol < ml)) { mv = ov; ml = ol; }
            }
            topsum += mv; kth = mv;
            if (d == ml) tmp = -1.f;
        }
        bool keep = (a >= kth);
        unsigned bal = __ballot_sync(0xffffffffu, keep && lane < 16) & 0xFFFFu;
        int pos = __popc(bal & ((1u << lane) - 1u));
        float inv = 1.f / topsum;
        size_t base = ((size_t)i * HH + h) * 8;
        if (lane < 16 && keep && pos < 8) {
            tidx[base + pos] = s;
            tw[base + pos]   = a * inv;
        }
        int cnt = __popc(bal); if (cnt > 8) cnt = 8;
        int fl = __ffs(bal) - 1;
        int s0 = __shfl_sync(0xffffffffu, s, fl);
        if (lane == 0) {
            for (int p = cnt; p < 8; p++) { tidx[base + p] = s0; tw[base + p] = 0.f; }
        }
    }
}

// ---------------- one PPR hop: out = 0.9 * A_sparse @ in + 0.1 * feat0 ----------------
__global__ void hop_kernel(const float* __restrict__ fin, float* __restrict__ fout,
                           const float* __restrict__ f0,
                           const int* __restrict__ tidx, const float* __restrict__ tw) {
    int i = blockIdx.x;
    int t = threadIdx.x;                 // 256 = h*32 + k
    __shared__ int   sidx[64];
    __shared__ float sw[64];
    if (t < 64) { sidx[t] = tidx[(size_t)i * 64 + t]; sw[t] = tw[(size_t)i * 64 + t]; }
    __syncthreads();
    int h = t >> 5;
    const int*   ix = sidx + h * 8;
    const float* w  = sw   + h * 8;
    float acc = 0.f;
#pragma unroll
    for (int s2 = 0; s2 < 8; s2++)
        acc += w[s2] * __ldg(&fin[(size_t)ix[s2] * FF + t]);
    fout[(size_t)i * FF + t] = 0.9f * acc + 0.1f * f0[(size_t)i * FF + t];
}

// ---------------- generic SGEMM: C = A[M,K] @ B[K,Nc] (+bias)(+relu)(+res) ----------------
template <bool BIAS, bool RELU, bool RES>
__global__ __launch_bounds__(256) void sgemm128(const float* __restrict__ A,
                                                const float* __restrict__ B,
                                                const float* __restrict__ bias,
                                                const float* __restrict__ res,
                                                float* __restrict__ C,
                                                int M, int K, int Nc) {
    const int BM = 128, BN = 128, BK = 8;
    __shared__ float As[BK][BM];
    __shared__ float Bs[BK][BN];
    int tid = threadIdx.x;
    int tx = tid & 15, ty = tid >> 4;
    int bm = blockIdx.y * BM, bn = blockIdx.x * BN;

    float acc[8][8];
#pragma unroll
    for (int a0 = 0; a0 < 8; a0++)
#pragma unroll
        for (int b0 = 0; b0 < 8; b0++) acc[a0][b0] = 0.f;

    int am = tid >> 1;          // 0..127
    int ak = (tid & 1) * 4;     // 0 or 4
    int bk = tid >> 5;          // 0..7
    int bn4 = (tid & 31) * 4;   // 0..124

    bool arow_ok = (bm + am) < M;
    const float* Aptr = A + (size_t)(bm + am) * K + ak;
    const float* Bptr = B + (size_t)bk * Nc + bn + bn4;

    for (int k0 = 0; k0 < K; k0 += BK) {
        float4 av = arow_ok ? *(const float4*)Aptr : make_float4(0.f, 0.f, 0.f, 0.f);
        float4 bv = *(const float4*)Bptr;
        __syncthreads();
        As[ak + 0][am] = av.x; As[ak + 1][am] = av.y;
        As[ak + 2][am] = av.z; As[ak + 3][am] = av.w;
        *(float4*)&Bs[bk][bn4] = bv;
        __syncthreads();
#pragma unroll
        for (int k = 0; k < BK; k++) {
            float ra[8], rb[8];
#pragma unroll
            for (int j = 0; j < 8; j++) ra[j] = As[k][ty * 8 + j];
#pragma unroll
            for (int j = 0; j < 8; j++) rb[j] = Bs[k][tx * 8 + j];
#pragma unroll
            for (int im = 0; im < 8; im++)
#pragma unroll
                for (int in = 0; in < 8; in++) acc[im][in] += ra[im] * rb[in];
        }
        Aptr += BK;
        Bptr += (size_t)BK * Nc;
    }
#pragma unroll
    for (int im = 0; im < 8; im++) {
        int row = bm + ty * 8 + im;
        if (row >= M) continue;
#pragma unroll
        for (int in = 0; in < 8; in++) {
            int col = bn + tx * 8 + in;
            float v = acc[im][in];
            if (BIAS) v += bias[col];
            if (RELU) v = fmaxf(v, 0.f);
            if (RES)  v += res[(size_t)row * Nc + col];
            C[(size_t)row * Nc + col] = v;
        }
    }
}

// ---------------- host launch ----------------
static inline void* sym(const void* s) {
    void* p = nullptr;
    cudaGetSymbolAddress(&p, s);
    return p;
}

extern "C" void kernel_launch(void* const* d_in, const int* in_sizes, int n_in,
                              void* d_out, int out_size) {
    const float* ent      = (const float*)d_in[0];
    const float* rel      = (const float*)d_in[1];
    const float* W_head   = (const float*)d_in[2];
    const float* W_tail   = (const float*)d_in[3];
    const float* W_ent    = (const float*)d_in[4];
    const float* W_rel    = (const float*)d_in[5];
    const float* attn_h   = (const float*)d_in[6];
    const float* attn_t   = (const float*)d_in[7];
    const float* attn_r   = (const float*)d_in[8];
    const float* ln_ent_g = (const float*)d_in[9];
    const float* ln_ent_b = (const float*)d_in[10];
    const float* ln_rel_g = (const float*)d_in[11];
    const float* ln_rel_b = (const float*)d_in[12];
    const float* ln_ff_g  = (const float*)d_in[13];
    const float* ln_ff_b  = (const float*)d_in[14];
    const float* ffn_W1   = (const float*)d_in[15];
    const float* ffn_b1   = (const float*)d_in[16];
    const float* ffn_W2   = (const float*)d_in[17];
    const float* ffn_b2   = (const float*)d_in[18];
    const int*   src      = (const int*)d_in[19];
    const int*   rid      = (const int*)d_in[20];
    float* out = (float*)d_out;

    float* x   = (float*)sym(g_x);
    float* rln = (float*)sym(g_rln);
    float* fe  = (float*)sym(g_fe);
    float* fA  = (float*)sym(g_fA);
    float* fB  = (float*)sym(g_fB);
    float* eh  = (float*)sym(g_eh);
    float* et  = (float*)sym(g_et);
    float* er  = (float*)sym(g_er);
    float* Ah  = (float*)sym(g_Ah);
    float* At  = (float*)sym(g_At);
    float* Ar  = (float*)sym(g_Ar);
    int*   tix = (int*)sym(g_tidx);
    float* tw  = (float*)sym(g_tw);
    float* rst = (float*)sym(g_rst);
    float* y   = (float*)sym(g_y);
    float* hid = (float*)sym(g_hid);

    // attention-vector folding (kills the fh/ftl GEMMs entirely)
    reduce_attn_kernel<<<8, 256>>>(W_head, attn_h, Ah);
    reduce_attn_kernel<<<8, 256>>>(W_tail, attn_t, At);
    reduce_attn_kernel<<<8, 256>>>(W_rel,  attn_r, Ar);

    // layer norms
    ln_kernel<<<NN, 256>>>(ent, nullptr, ln_ent_g, ln_ent_b, x, nullptr, NN);
    ln_kernel<<<RR, 256>>>(rel, nullptr, ln_rel_g, ln_rel_b, rln, nullptr, RR);

    // logits
    dot_heads_kernel<<<NN, 256>>>(x, Ah, At, eh, et, NN);
    dot_heads_kernel<<<RR, 256>>>(rln, Ar, Ar, er, er, RR);

    // feat0 = x @ W_ent
    {
        dim3 grid(FF / 128, (NN + 127) / 128);
        sgemm128<false, false, false><<<grid, 256>>>(x, W_ent, nullptr, nullptr, fe, NN, FF, FF);
    }

    // edge softmax + top-k -> compacted sparse attention
    attn_topk_kernel<<<(NN * 32 + 255) / 256, 256>>>(eh, et, er, src, rid, tix, tw);

    // 10 PPR hops (ping-pong)
    for (int it = 0; it < HOPS; it++) {
        const float* fin = (it == 0) ? fe : ((it & 1) ? fA : fB);
        float* fout = (it & 1) ? fB : fA;
        hop_kernel<<<NN, 256>>>(fin, fout, fe, tix, tw);
    }
    // final feat is in fB (HOPS=10, last it=9 odd -> fB)

    // residual + LN
    ln_kernel<<<NN, 256>>>(fB, ent, ln_ff_g, ln_ff_b, y, rst, NN);

    // FFN
    {
        dim3 grid1(FHID / 128, (NN + 127) / 128);
        sgemm128<true, true, false><<<grid1, 256>>>(y, ffn_W1, ffn_b1, nullptr, hid, NN, FF, FHID);
        dim3 grid2(FF / 128, (NN + 127) / 128);
        sgemm128<true, false, true><<<grid2, 256>>>(hid, ffn_W2, ffn_b2, rst, out, NN, FHID, FF);
    }
}

// round 2
// speedup vs baseline: 1.2927x; 1.2927x over previous
#include <cuda_runtime.h>
#include <cuda_bf16.h>
#include <cstddef>

#define NN 50000
#define FF 256
#define HH 8
#define DHH 32
#define DD 16
#define RR 20
#define FHID 1024
#define HOPS 10

// ---------------- scratch (static device globals; no allocation) ----------------
__device__ float g_x[NN * FF];         // LN'd ent_feat
__device__ float g_rln[RR * FF];       // LN'd rel_feat
__device__ float g_fe[NN * FF];        // feat0 = x @ W_ent
__device__ float g_fA[NN * FF];        // ping
__device__ float g_fB[NN * FF];        // pong
__device__ float g_eh[NN * HH];
__device__ float g_et[NN * HH];
__device__ float g_er[RR * HH];
__device__ float g_Ah[FF * HH];
__device__ float g_At[FF * HH];
__device__ float g_Ar[FF * HH];
__device__ int   g_tidx[NN * HH * 8];  // compacted top-k src indices
__device__ float g_tw[NN * HH * 8];    // compacted renormalized weights
__device__ float g_rst[NN * FF];
__device__ float g_y[NN * FF];
__device__ float g_hid[(size_t)NN * FHID];

// ---------------- A[f,h] = sum_dh W[f, h*DH+dh] * attn[h,dh] ----------------
__global__ void reduce_attn_kernel(const float* __restrict__ W,
                                   const float* __restrict__ attn,
                                   float* __restrict__ A) {
    int idx = blockIdx.x * blockDim.x + threadIdx.x;
    if (idx >= FF * HH) return;
    int f = idx / HH, h = idx % HH;
    float s = 0.f;
#pragma unroll
    for (int d = 0; d < DHH; d++)
        s += W[(size_t)f * (HH * DHH) + h * DHH + d] * attn[h * DHH + d];
    A[f * HH + h] = s;
}

// ---------------- LayerNorm over F=256 (optionally add residual input first) ----------------
__global__ void ln_kernel(const float* __restrict__ X, const float* __restrict__ add,
                          const float* __restrict__ g, const float* __restrict__ b,
                          float* __restrict__ Y, float* __restrict__ rstOut, int rows) {
    int i = blockIdx.x;
    if (i >= rows) return;
    int t = threadIdx.x;                // 256 threads
    float v = X[(size_t)i * FF + t];
    if (add) v += add[(size_t)i * FF + t];
    if (rstOut) rstOut[(size_t)i * FF + t] = v;

    __shared__ float red[8];
    int lane = t & 31, wid = t >> 5;
    float s = v;
#pragma unroll
    for (int o = 16; o; o >>= 1) s += __shfl_xor_sync(0xffffffffu, s, o);
    if (lane == 0) red[wid] = s;
    __syncthreads();
    float tot = 0.f;
#pragma unroll
    for (int w = 0; w < 8; w++) tot += red[w];
    float mean = tot * (1.f / FF);
    float d = v - mean;
    __syncthreads();
    s = d * d;
#pragma unroll
    for (int o = 16; o; o >>= 1) s += __shfl_xor_sync(0xffffffffu, s, o);
    if (lane == 0) red[wid] = s;
    __syncthreads();
    tot = 0.f;
#pragma unroll
    for (int w = 0; w < 8; w++) tot += red[w];
    float var = tot * (1.f / FF);
    Y[(size_t)i * FF + t] = d * rsqrtf(var + 1e-5f) * g[t] + b[t];
}

// ---------------- per-row 8-head dot products: o1 = X@A1, o2 = X@A2 ----------------
__global__ void dot_heads_kernel(const float* __restrict__ X,
                                 const float* __restrict__ A1, const float* __restrict__ A2,
                                 float* __restrict__ o1, float* __restrict__ o2, int rows) {
    int i = blockIdx.x;
    if (i >= rows) return;
    int t = threadIdx.x;          // 256 threads; warp = head
    int h = t >> 5, lane = t & 31;
    float s1 = 0.f, s2 = 0.f;
#pragma unroll
    for (int j = 0; j < 8; j++) {
        int f = lane + 32 * j;
        float x = X[(size_t)i * FF + f];
        s1 += x * A1[f * HH + h];
        s2 += x * A2[f * HH + h];
    }
#pragma unroll
    for (int o = 16; o; o >>= 1) {
        s1 += __shfl_xor_sync(0xffffffffu, s1, o);
        s2 += __shfl_xor_sync(0xffffffffu, s2, o);
    }
    if (lane == 0) { o1[i * HH + h] = s1; o2[i * HH + h] = s2; }
}

// ---------------- edge softmax + top-5 sparsify + renormalize, compacted ----------------
__global__ void attn_topk_kernel(const float* __restrict__ eh, const float* __restrict__ et,
                                 const float* __restrict__ er,
                                 const int* __restrict__ src, const int* __restrict__ rid,
                                 int* __restrict__ tidx, float* __restrict__ tw) {
    int warp = (blockIdx.x * blockDim.x + threadIdx.x) >> 5;
    if (warp >= NN) return;
    int lane = threadIdx.x & 31;
    int d = lane & 15;                        // lanes 16..31 mirror 0..15
    int i = warp;
    int s  = src[i * DD + d];
    int rd = rid[i * DD + d];
#pragma unroll
    for (int h = 0; h < HH; h++) {
        float e = eh[s * HH + h] + et[i * HH + h] + er[rd * HH + h];
        e = e > 0.f ? e : 0.2f * e;           // LeakyReLU
        float m = e;
#pragma unroll
        for (int o = 8; o; o >>= 1) m = fmaxf(m, __shfl_xor_sync(0xffffffffu, m, o, 16));
        float a = __expf(e - m);
        float ssum = a;
#pragma unroll
        for (int o = 8; o; o >>= 1) ssum += __shfl_xor_sync(0xffffffffu, ssum, o, 16);
        a /= ssum;
        // iterative top-5 (distinct lanes; duplicate values counted like lax.top_k)
        float tmp = a, topsum = 0.f, kth = 0.f;
#pragma unroll
        for (int it = 0; it < 5; it++) {
            float mv = tmp; int ml = d;
#pragma unroll
            for (int o = 8; o; o >>= 1) {
                float ov = __shfl_xor_sync(0xffffffffu, mv, o, 16);
                int   ol = __shfl_xor_sync(0xffffffffu, ml, o, 16);
                if (ov > mv || (ov == mv && ol < ml)) { mv = ov; ml = ol; }
            }
            topsum += mv; kth = mv;
            if (d == ml) tmp = -1.f;
        }
        bool keep = (a >= kth);
        unsigned bal = __ballot_sync(0xffffffffu, keep && lane < 16) & 0xFFFFu;
        int pos = __popc(bal & ((1u << lane) - 1u));
        float inv = 1.f / topsum;
        size_t base = ((size_t)i * HH + h) * 8;
        if (lane < 16 && keep && pos < 8) {
            tidx[base + pos] = s;
            tw[base + pos]   = a * inv;
        }
        int cnt = __popc(bal); if (cnt > 8) cnt = 8;
        int fl = __ffs(bal) - 1;
        int s0 = __shfl_sync(0xffffffffu, s, fl);
        if (lane == 0) {
            for (int p = cnt; p < 8; p++) { tidx[base + p] = s0; tw[base + p] = 0.f; }
        }
    }
}

// ---------------- one PPR hop: out = 0.9 * A_sparse @ in + 0.1 * feat0 ----------------
__global__ void hop_kernel(const float* __restrict__ fin, float* __restrict__ fout,
                           const float* __restrict__ f0,
                           const int* __restrict__ tidx, const float* __restrict__ tw) {
    int i = blockIdx.x;
    int t = threadIdx.x;                 // 256 = h*32 + lane
    __shared__ int   sidx[64];
    __shared__ float sw[64];
    if (t < 64) { sidx[t] = tidx[(size_t)i * 64 + t]; sw[t] = tw[(size_t)i * 64 + t]; }
    __syncthreads();
    int h = t >> 5;
    const int*   ix = sidx + h * 8;
    const float* w  = sw   + h * 8;
    float acc = 0.f;
#pragma unroll
    for (int s2 = 0; s2 < 8; s2++) {
        float ws = w[s2];
        if (ws != 0.f)                    // warp-uniform skip (usually 3 of 8 skipped)
            acc += ws * __ldg(&fin[(size_t)ix[s2] * FF + t]);
    }
    fout[(size_t)i * FF + t] = 0.9f * acc + 0.1f * f0[(size_t)i * FF + t];
}

// ---------------- TF32 tensor-core GEMM: C = A[M,K] @ B[K,Nc] (+bias)(+relu)(+res) ----------------
__device__ __forceinline__ float to_tf32(float x) {
    unsigned r;
    asm("cvt.rna.tf32.f32 %0, %1;" : "=r"(r) : "f"(x));
    return __uint_as_float(r);
}
__device__ __forceinline__ float4 cvt4(float4 v) {
    v.x = to_tf32(v.x); v.y = to_tf32(v.y); v.z = to_tf32(v.z); v.w = to_tf32(v.w);
    return v;
}

template <bool BIAS, bool RELU, bool RES>
__global__ __launch_bounds__(256) void tf32_gemm(const float* __restrict__ A,
                                                 const float* __restrict__ B,
                                                 const float* __restrict__ bias,
                                                 const float* __restrict__ res,
                                                 float* __restrict__ C,
                                                 int M, int K, int Nc) {
    // BM=128, BN=128, BK=16; 8 warps, each computes 32x64 via m16n8k8 tf32 mma
    __shared__ __align__(16) float As[128][20];   // pad 20: conflict-free frag loads
    __shared__ __align__(16) float Bs[16][136];   // pad 136 (mod 32 == 8): conflict-free

    int tid = threadIdx.x;
    int wid = tid >> 5, lane = tid & 31;
    int g = lane >> 2, t4 = lane & 3;
    int warpRow = (wid >> 1) * 32, warpCol = (wid & 1) * 64;
    int bm = blockIdx.y * 128, bn = blockIdx.x * 128;

    float acc[2][8][4];
#pragma unroll
    for (int a0 = 0; a0 < 2; a0++)
#pragma unroll
        for (int b0 = 0; b0 < 8; b0++)
#pragma unroll
            for (int c0 = 0; c0 < 4; c0++) acc[a0][b0][c0] = 0.f;

    // global->smem mapping: 512 float4 per tile, 2 per thread
    int aRow = tid >> 1;              // 0..127
    int aC = (tid & 1) * 2;           // float4 slot base (0 or 2)
    int bRow = tid >> 4;              // 0..15
    int bC = (tid * 2) & 31;          // float4 slot base

    bool aok = (bm + aRow) < M;
    const float* Ap = A + (size_t)(bm + aRow) * K + aC * 4;
    const float* Bp = B + (size_t)bRow * Nc + bn + bC * 4;

    int iters = K >> 4;
    float4 av[2], bv[2];
    const float4 z4 = make_float4(0.f, 0.f, 0.f, 0.f);
#pragma unroll
    for (int j = 0; j < 2; j++) {
        av[j] = aok ? *(const float4*)(Ap + j * 4) : z4;
        bv[j] = *(const float4*)(Bp + j * 4);
    }

    for (int it = 0; it < iters; it++) {
        __syncthreads();
#pragma unroll
        for (int j = 0; j < 2; j++) {
            *(float4*)&As[aRow][(aC + j) * 4] = cvt4(av[j]);
            *(float4*)&Bs[bRow][(bC + j) * 4] = cvt4(bv[j]);
        }
        __syncthreads();
        if (it + 1 < iters) {
            const float* Ap2 = Ap + (size_t)(it + 1) * 16;
            const float* Bp2 = Bp + (size_t)(it + 1) * 16 * Nc;
#pragma unroll
            for (int j = 0; j < 2; j++) {
                av[j] = aok ? *(const float4*)(Ap2 + j * 4) : z4;
                bv[j] = *(const float4*)(Bp2 + j * 4);
            }
        }
#pragma unroll
        for (int k8 = 0; k8 < 16; k8 += 8) {
            unsigned af[2][4];
#pragma unroll
            for (int mt = 0; mt < 2; mt++) {
                int r0 = warpRow + mt * 16 + g;
                af[mt][0] = __float_as_uint(As[r0][k8 + t4]);
                af[mt][1] = __float_as_uint(As[r0 + 8][k8 + t4]);
                af[mt][2] = __float_as_uint(As[r0][k8 + t4 + 4]);
                af[mt][3] = __float_as_uint(As[r0 + 8][k8 + t4 + 4]);
            }
#pragma unroll
            for (int nt = 0; nt < 8; nt++) {
                int c = warpCol + nt * 8 + g;
                unsigned b0 = __float_as_uint(Bs[k8 + t4][c]);
                unsigned b1 = __float_as_uint(Bs[k8 + t4 + 4][c]);
#pragma unroll
                for (int mt = 0; mt < 2; mt++) {
                    asm volatile(
                        "mma.sync.aligned.m16n8k8.row.col.f32.tf32.tf32.f32 "
                        "{%0,%1,%2,%3}, {%4,%5,%6,%7}, {%8,%9}, {%0,%1,%2,%3};\n"
                        : "+f"(acc[mt][nt][0]), "+f"(acc[mt][nt][1]),
                          "+f"(acc[mt][nt][2]), "+f"(acc[mt][nt][3])
                        : "r"(af[mt][0]), "r"(af[mt][1]), "r"(af[mt][2]), "r"(af[mt][3]),
                          "r"(b0), "r"(b1));
                }
            }
        }
    }

    // epilogue
#pragma unroll
    for (int mt = 0; mt < 2; mt++) {
#pragma unroll
        for (int nt = 0; nt < 8; nt++) {
            int row = bm + warpRow + mt * 16 + g;
            int col = bn + warpCol + nt * 8 + 2 * t4;
#pragma unroll
            for (int half = 0; half < 2; half++) {
                int r = row + half * 8;
                if (r >= M) continue;
                float v0 = acc[mt][nt][half * 2 + 0];
                float v1 = acc[mt][nt][half * 2 + 1];
                if (BIAS) { v0 += bias[col]; v1 += bias[col + 1]; }
                if (RELU) { v0 = fmaxf(v0, 0.f); v1 = fmaxf(v1, 0.f); }
                if (RES) {
                    float2 rv = *(const float2*)&res[(size_t)r * Nc + col];
                    v0 += rv.x; v1 += rv.y;
                }
                float2 o; o.x = v0; o.y = v1;
                *(float2*)&C[(size_t)r * Nc + col] = o;
            }
        }
    }
}

// ---------------- host launch ----------------
static inline void* sym(const void* s) {
    void* p = nullptr;
    cudaGetSymbolAddress(&p, s);
    return p;
}

extern "C" void kernel_launch(void* const* d_in, const int* in_sizes, int n_in,
                              void* d_out, int out_size) {
    const float* ent      = (const float*)d_in[0];
    const float* rel      = (const float*)d_in[1];
    const float* W_head   = (const float*)d_in[2];
    const float* W_tail   = (const float*)d_in[3];
    const float* W_ent    = (const float*)d_in[4];
    const float* W_rel    = (const float*)d_in[5];
    const float* attn_h   = (const float*)d_in[6];
    const float* attn_t   = (const float*)d_in[7];
    const float* attn_r   = (const float*)d_in[8];
    const float* ln_ent_g = (const float*)d_in[9];
    const float* ln_ent_b = (const float*)d_in[10];
    const float* ln_rel_g = (const float*)d_in[11];
    const float* ln_rel_b = (const float*)d_in[12];
    const float* ln_ff_g  = (const float*)d_in[13];
    const float* ln_ff_b  = (const float*)d_in[14];
    const float* ffn_W1   = (const float*)d_in[15];
    const float* ffn_b1   = (const float*)d_in[16];
    const float* ffn_W2   = (const float*)d_in[17];
    const float* ffn_b2   = (const float*)d_in[18];
    const int*   src      = (const int*)d_in[19];
    const int*   rid      = (const int*)d_in[20];
    float* out = (float*)d_out;

    float* x   = (float*)sym(g_x);
    float* rln = (float*)sym(g_rln);
    float* fe  = (float*)sym(g_fe);
    float* fA  = (float*)sym(g_fA);
    float* fB  = (float*)sym(g_fB);
    float* eh  = (float*)sym(g_eh);
    float* et  = (float*)sym(g_et);
    float* er  = (float*)sym(g_er);
    float* Ah  = (float*)sym(g_Ah);
    float* At  = (float*)sym(g_At);
    float* Ar  = (float*)sym(g_Ar);
    int*   tix = (int*)sym(g_tidx);
    float* tw  = (float*)sym(g_tw);
    float* rst = (float*)sym(g_rst);
    float* y   = (float*)sym(g_y);
    float* hid = (float*)sym(g_hid);

    // attention-vector folding (kills the fh/ftl GEMMs entirely)
    reduce_attn_kernel<<<8, 256>>>(W_head, attn_h, Ah);
    reduce_attn_kernel<<<8, 256>>>(W_tail, attn_t, At);
    reduce_attn_kernel<<<8, 256>>>(W_rel,  attn_r, Ar);

    // layer norms
    ln_kernel<<<NN, 256>>>(ent, nullptr, ln_ent_g, ln_ent_b, x, nullptr, NN);
    ln_kernel<<<RR, 256>>>(rel, nullptr, ln_rel_g, ln_rel_b, rln, nullptr, RR);

    // logits
    dot_heads_kernel<<<NN, 256>>>(x, Ah, At, eh, et, NN);
    dot_heads_kernel<<<RR, 256>>>(rln, Ar, Ar, er, er, RR);

    // feat0 = x @ W_ent   (tensor cores, tf32)
    {
        dim3 grid(FF / 128, (NN + 127) / 128);
        tf32_gemm<false, false, false><<<grid, 256>>>(x, W_ent, nullptr, nullptr, fe, NN, FF, FF);
    }

    // edge softmax + top-k -> compacted sparse attention
    attn_topk_kernel<<<(NN * 32 + 255) / 256, 256>>>(eh, et, er, src, rid, tix, tw);

    // 10 PPR hops (ping-pong)
    for (int it = 0; it < HOPS; it++) {
        const float* fin = (it == 0) ? fe : ((it & 1) ? fA : fB);
        float* fout = (it & 1) ? fB : fA;
        hop_kernel<<<NN, 256>>>(fin, fout, fe, tix, tw);
    }
    // final feat in fB (last it = 9, odd -> fB)

    // residual + LN
    ln_kernel<<<NN, 256>>>(fB, ent, ln_ff_g, ln_ff_b, y, rst, NN);

    // FFN (tensor cores, tf32)
    {
        dim3 grid1(FHID / 128, (NN + 127) / 128);
        tf32_gemm<true, true, false><<<grid1, 256>>>(y, ffn_W1, ffn_b1, nullptr, hid, NN, FF, FHID);
        dim3 grid2(FF / 128, (NN + 127) / 128);
        tf32_gemm<true, false, true><<<grid2, 256>>>(hid, ffn_W2, ffn_b2, rst, out, NN, FHID, FF);
    }
}

// round 8
// speedup vs baseline: 1.3414x; 1.0377x over previous
#include <cuda_runtime.h>
#include <cuda_fp16.h>
#include <cuda_bf16.h>
#include <cstddef>

#define NN 50000
#define FF 256
#define HH 8
#define DHH 32
#define DD 16
#define RR 20
#define FHID 1024
#define HOPS 10

// ---------------- scratch (static device globals; no allocation) ----------------
__device__ float  g_x[NN * FF];          // LN'd ent_feat
__device__ float  g_rln[RR * FF];        // LN'd rel_feat
__device__ float  g_fe[NN * FF];         // feat0 = x @ W_ent (fp32, from GEMM)
__device__ __half g_fe16[NN * FF];       // feat0 cast to fp16
__device__ __half g_fA16[NN * FF];       // ping (fp16)
__device__ __half g_fB16[NN * FF];       // pong (fp16)
__device__ float  g_eh[NN * HH];
__device__ float  g_et[NN * HH];
__device__ float  g_er[RR * HH];
__device__ float  g_Ah[FF * HH];
__device__ float  g_At[FF * HH];
__device__ float  g_Ar[FF * HH];
__device__ int    g_tidx[NN * HH * 8];   // compacted top-k src indices
__device__ float  g_tw[NN * HH * 8];     // compacted renormalized weights
__device__ float  g_rst[NN * FF];
__device__ float  g_y[NN * FF];
__device__ float  g_hid[(size_t)NN * FHID];

// ---------------- A[f,h] = sum_dh W[f, h*DH+dh] * attn[h,dh] ----------------
__global__ void reduce_attn_kernel(const float* __restrict__ W,
                                   const float* __restrict__ attn,
                                   float* __restrict__ A) {
    int idx = blockIdx.x * blockDim.x + threadIdx.x;
    if (idx >= FF * HH) return;
    int f = idx / HH, h = idx % HH;
    float s = 0.f;
#pragma unroll
    for (int d = 0; d < DHH; d++)
        s += W[(size_t)f * (HH * DHH) + h * DHH + d] * attn[h * DHH + d];
    A[f * HH + h] = s;
}

// ---------------- fp32 -> fp16 cast ----------------
__global__ void cast_kernel(const float* __restrict__ in, __half* __restrict__ out, int n) {
    int i = blockIdx.x * blockDim.x + threadIdx.x;
    if (i < n) out[i] = __float2half_rn(in[i]);
}

// ---------------- single-pass LayerNorm over F=256 (optional residual add, fp32 or fp16 input) ----------------
template <bool XHALF>
__global__ void ln_kernel(const void* __restrict__ Xv, const float* __restrict__ add,
                          const float* __restrict__ g, const float* __restrict__ b,
                          float* __restrict__ Y, float* __restrict__ rstOut, int rows) {
    int i = blockIdx.x;
    if (i >= rows) return;
    int t = threadIdx.x;                // 256 threads
    float v;
    if (XHALF) v = __half2float(((const __half*)Xv)[(size_t)i * FF + t]);
    else       v = ((const float*)Xv)[(size_t)i * FF + t];
    if (add) v += add[(size_t)i * FF + t];
    if (rstOut) rstOut[(size_t)i * FF + t] = v;

    __shared__ float r1[8], r2[8];
    int lane = t & 31, wid = t >> 5;
    float s = v, s2 = v * v;
#pragma unroll
    for (int o = 16; o; o >>= 1) {
        s  += __shfl_xor_sync(0xffffffffu, s, o);
        s2 += __shfl_xor_sync(0xffffffffu, s2, o);
    }
    if (lane == 0) { r1[wid] = s; r2[wid] = s2; }
    __syncthreads();
    float S1 = 0.f, S2 = 0.f;
#pragma unroll
    for (int w = 0; w < 8; w++) { S1 += r1[w]; S2 += r2[w]; }
    float mean = S1 * (1.f / FF);
    float var = S2 * (1.f / FF) - mean * mean;
    Y[(size_t)i * FF + t] = (v - mean) * rsqrtf(var + 1e-5f) * g[t] + b[t];
}

// ---------------- per-row 8-head dot products: o1 = X@A1, o2 = X@A2 ----------------
__global__ void dot_heads_kernel(const float* __restrict__ X,
                                 const float* __restrict__ A1, const float* __restrict__ A2,
                                 float* __restrict__ o1, float* __restrict__ o2, int rows) {
    int i = blockIdx.x;
    if (i >= rows) return;
    int t = threadIdx.x;          // 256 threads; warp = head
    int h = t >> 5, lane = t & 31;
    float s1 = 0.f, s2 = 0.f;
#pragma unroll
    for (int j = 0; j < 8; j++) {
        int f = lane + 32 * j;
        float x = X[(size_t)i * FF + f];
        s1 += x * A1[f * HH + h];
        s2 += x * A2[f * HH + h];
    }
#pragma unroll
    for (int o = 16; o; o >>= 1) {
        s1 += __shfl_xor_sync(0xffffffffu, s1, o);
        s2 += __shfl_xor_sync(0xffffffffu, s2, o);
    }
    if (lane == 0) { o1[i * HH + h] = s1; o2[i * HH + h] = s2; }
}

// ---------------- edge softmax + top-5 sparsify + renormalize, compacted ----------------
__global__ void attn_topk_kernel(const float* __restrict__ eh, const float* __restrict__ et,
                                 const float* __restrict__ er,
                                 const int* __restrict__ src, const int* __restrict__ rid,
                                 int* __restrict__ tidx, float* __restrict__ tw) {
    int warp = (blockIdx.x * blockDim.x + threadIdx.x) >> 5;
    if (warp >= NN) return;
    int lane = threadIdx.x & 31;
    int d = lane & 15;                        // lanes 16..31 mirror 0..15
    int i = warp;
    int s  = src[i * DD + d];
    int rd = rid[i * DD + d];
#pragma unroll
    for (int h = 0; h < HH; h++) {
        float e = eh[s * HH + h] + et[i * HH + h] + er[rd * HH + h];
        e = e > 0.f ? e : 0.2f * e;           // LeakyReLU
        float m = e;
#pragma unroll
        for (int o = 8; o; o >>= 1) m = fmaxf(m, __shfl_xor_sync(0xffffffffu, m, o, 16));
        float a = __expf(e - m);
        float ssum = a;
#pragma unroll
        for (int o = 8; o; o >>= 1) ssum += __shfl_xor_sync(0xffffffffu, ssum, o, 16);
        a /= ssum;
        // iterative top-5 (distinct lanes; duplicate values counted like lax.top_k)
        float tmp = a, topsum = 0.f, kth = 0.f;
#pragma unroll
        for (int it = 0; it < 5; it++) {
            float mv = tmp; int ml = d;
#pragma unroll
            for (int o = 8; o; o >>= 1) {
                float ov = __shfl_xor_sync(0xffffffffu, mv, o, 16);
                int   ol = __shfl_xor_sync(0xffffffffu, ml, o, 16);
                if (ov > mv || (ov == mv && ol < ml)) { mv = ov; ml = ol; }
            }
            topsum += mv; kth = mv;
            if (d == ml) tmp = -1.f;
        }
        bool keep = (a >= kth);
        unsigned bal = __ballot_sync(0xffffffffu, keep && lane < 16) & 0xFFFFu;
        int pos = __popc(bal & ((1u << lane) - 1u));
        float inv = 1.f / topsum;
        size_t base = ((size_t)i * HH + h) * 8;
        if (lane < 16 && keep && pos < 8) {
            tidx[base + pos] = s;
            tw[base + pos]   = a * inv;
        }
        int cnt = __popc(bal); if (cnt > 8) cnt = 8;
        int fl = __ffs(bal) - 1;
        int s0 = __shfl_sync(0xffffffffu, s, fl);
        if (lane == 0) {
            for (int p = cnt; p < 8; p++) { tidx[base + p] = s0; tw[base + p] = 0.f; }
        }
    }
}

// ---------------- one PPR hop (fp16 storage, fp32 math): out = 0.9 * A_sparse @ in + 0.1 * feat0 ----------------
// Same structure as the R2-passing fp32 hop: 1 node per block, thread t = feature t.
__global__ void hop_kernel(const __half* __restrict__ fin, __half* __restrict__ fout,
                           const __half* __restrict__ f0,
                           const int* __restrict__ tidx, const float* __restrict__ tw) {
    int i = blockIdx.x;
    int t = threadIdx.x;                 // 256 = h*32 + lane
    __shared__ int   sidx[64];
    __shared__ float sw[64];
    if (t < 64) { sidx[t] = tidx[(size_t)i * 64 + t]; sw[t] = tw[(size_t)i * 64 + t]; }
    __syncthreads();
    int h = t >> 5;
    const int*   ix = sidx + h * 8;
    const float* w  = sw   + h * 8;
    float acc = 0.f;
#pragma unroll
    for (int s2 = 0; s2 < 8; s2++) {
        float ws = w[s2];
        if (ws != 0.f)                    // warp-uniform skip (usually 3 of 8 skipped)
            acc += ws * __half2float(__ldg(&fin[(size_t)ix[s2] * FF + t]));
    }
    float z = __half2float(f0[(size_t)i * FF + t]);
    fout[(size_t)i * FF + t] = __float2half_rn(0.9f * acc + 0.1f * z);
}

// ---------------- TF32 tensor-core GEMM: C = A[M,K] @ B[K,Nc] (+bias)(+relu)(+res) ----------------
// (byte-identical to the R2-passing version)
__device__ __forceinline__ float to_tf32(float x) {
    unsigned r;
    asm("cvt.rna.tf32.f32 %0, %1;" : "=r"(r) : "f"(x));
    return __uint_as_float(r);
}
__device__ __forceinline__ float4 cvt4(float4 v) {
    v.x = to_tf32(v.x); v.y = to_tf32(v.y); v.z = to_tf32(v.z); v.w = to_tf32(v.w);
    return v;
}

template <bool BIAS, bool RELU, bool RES>
__global__ __launch_bounds__(256) void tf32_gemm(const float* __restrict__ A,
                                                 const float* __restrict__ B,
                                                 const float* __restrict__ bias,
                                                 const float* __restrict__ res,
                                                 float* __restrict__ C,
                                                 int M, int K, int Nc) {
    // BM=128, BN=128, BK=16; 8 warps, each computes 32x64 via m16n8k8 tf32 mma
    __shared__ __align__(16) float As[128][20];   // pad 20: conflict-free frag loads
    __shared__ __align__(16) float Bs[16][136];   // pad 136 (mod 32 == 8): conflict-free

    int tid = threadIdx.x;
    int wid = tid >> 5, lane = tid & 31;
    int g = lane >> 2, t4 = lane & 3;
    int warpRow = (wid >> 1) * 32, warpCol = (wid & 1) * 64;
    int bm = blockIdx.y * 128, bn = blockIdx.x * 128;

    float acc[2][8][4];
#pragma unroll
    for (int a0 = 0; a0 < 2; a0++)
#pragma unroll
        for (int b0 = 0; b0 < 8; b0++)
#pragma unroll
            for (int c0 = 0; c0 < 4; c0++) acc[a0][b0][c0] = 0.f;

    int aRow = tid >> 1;
    int aC = (tid & 1) * 2;
    int bRow = tid >> 4;
    int bC = (tid * 2) & 31;

    bool aok = (bm + aRow) < M;
    const float* Ap = A + (size_t)(bm + aRow) * K + aC * 4;
    const float* Bp = B + (size_t)bRow * Nc + bn + bC * 4;

    int iters = K >> 4;
    float4 av[2], bv[2];
    const float4 z4 = make_float4(0.f, 0.f, 0.f, 0.f);
#pragma unroll
    for (int j = 0; j < 2; j++) {
        av[j] = aok ? *(const float4*)(Ap + j * 4) : z4;
        bv[j] = *(const float4*)(Bp + j * 4);
    }

    for (int it = 0; it < iters; it++) {
        __syncthreads();
#pragma unroll
        for (int j = 0; j < 2; j++) {
            *(float4*)&As[aRow][(aC + j) * 4] = cvt4(av[j]);
            *(float4*)&Bs[bRow][(bC + j) * 4] = cvt4(bv[j]);
        }
        __syncthreads();
        if (it + 1 < iters) {
            const float* Ap2 = Ap + (size_t)(it + 1) * 16;
            const float* Bp2 = Bp + (size_t)(it + 1) * 16 * Nc;
#pragma unroll
            for (int j = 0; j < 2; j++) {
                av[j] = aok ? *(const float4*)(Ap2 + j * 4) : z4;
                bv[j] = *(const float4*)(Bp2 + j * 4);
            }
        }
#pragma unroll
        for (int k8 = 0; k8 < 16; k8 += 8) {
            unsigned af[2][4];
#pragma unroll
            for (int mt = 0; mt < 2; mt++) {
                int r0 = warpRow + mt * 16 + g;
                af[mt][0] = __float_as_uint(As[r0][k8 + t4]);
                af[mt][1] = __float_as_uint(As[r0 + 8][k8 + t4]);
                af[mt][2] = __float_as_uint(As[r0][k8 + t4 + 4]);
                af[mt][3] = __float_as_uint(As[r0 + 8][k8 + t4 + 4]);
            }
#pragma unroll
            for (int nt = 0; nt < 8; nt++) {
                int c = warpCol + nt * 8 + g;
                unsigned b0 = __float_as_uint(Bs[k8 + t4][c]);
                unsigned b1 = __float_as_uint(Bs[k8 + t4 + 4][c]);
#pragma unroll
                for (int mt = 0; mt < 2; mt++) {
                    asm volatile(
                        "mma.sync.aligned.m16n8k8.row.col.f32.tf32.tf32.f32 "
                        "{%0,%1,%2,%3}, {%4,%5,%6,%7}, {%8,%9}, {%0,%1,%2,%3};\n"
                        : "+f"(acc[mt][nt][0]), "+f"(acc[mt][nt][1]),
                          "+f"(acc[mt][nt][2]), "+f"(acc[mt][nt][3])
                        : "r"(af[mt][0]), "r"(af[mt][1]), "r"(af[mt][2]), "r"(af[mt][3]),
                          "r"(b0), "r"(b1));
                }
            }
        }
    }

    // epilogue
#pragma unroll
    for (int mt = 0; mt < 2; mt++) {
#pragma unroll
        for (int nt = 0; nt < 8; nt++) {
            int row = bm + warpRow + mt * 16 + g;
            int col = bn + warpCol + nt * 8 + 2 * t4;
#pragma unroll
            for (int half = 0; half < 2; half++) {
                int r = row + half * 8;
                if (r >= M) continue;
                float v0 = acc[mt][nt][half * 2 + 0];
                float v1 = acc[mt][nt][half * 2 + 1];
                if (BIAS) { v0 += bias[col]; v1 += bias[col + 1]; }
                if (RELU) { v0 = fmaxf(v0, 0.f); v1 = fmaxf(v1, 0.f); }
                if (RES) {
                    float2 rv = *(const float2*)&res[(size_t)r * Nc + col];
                    v0 += rv.x; v1 += rv.y;
                }
                float2 o; o.x = v0; o.y = v1;
                *(float2*)&C[(size_t)r * Nc + col] = o;
            }
        }
    }
}

// ---------------- host launch ----------------
static inline void* sym(const void* s) {
    void* p = nullptr;
    cudaGetSymbolAddress(&p, s);
    return p;
}

extern "C" void kernel_launch(void* const* d_in, const int* in_sizes, int n_in,
                              void* d_out, int out_size) {
    const float* ent      = (const float*)d_in[0];
    const float* rel      = (const float*)d_in[1];
    const float* W_head   = (const float*)d_in[2];
    const float* W_tail   = (const float*)d_in[3];
    const float* W_ent    = (const float*)d_in[4];
    const float* W_rel    = (const float*)d_in[5];
    const float* attn_h   = (const float*)d_in[6];
    const float* attn_t   = (const float*)d_in[7];
    const float* attn_r   = (const float*)d_in[8];
    const float* ln_ent_g = (const float*)d_in[9];
    const float* ln_ent_b = (const float*)d_in[10];
    const float* ln_rel_g = (const float*)d_in[11];
    const float* ln_rel_b = (const float*)d_in[12];
    const float* ln_ff_g  = (const float*)d_in[13];
    const float* ln_ff_b  = (const float*)d_in[14];
    const float* ffn_W1   = (const float*)d_in[15];
    const float* ffn_b1   = (const float*)d_in[16];
    const float* ffn_W2   = (const float*)d_in[17];
    const float* ffn_b2   = (const float*)d_in[18];
    const int*   src      = (const int*)d_in[19];
    const int*   rid      = (const int*)d_in[20];
    float* out = (float*)d_out;

    float*  x    = (float*)sym(g_x);
    float*  rln  = (float*)sym(g_rln);
    float*  fe   = (float*)sym(g_fe);
    __half* fe16 = (__half*)sym(g_fe16);
    __half* fA16 = (__half*)sym(g_fA16);
    __half* fB16 = (__half*)sym(g_fB16);
    float*  eh   = (float*)sym(g_eh);
    float*  et   = (float*)sym(g_et);
    float*  er   = (float*)sym(g_er);
    float*  Ah   = (float*)sym(g_Ah);
    float*  At   = (float*)sym(g_At);
    float*  Ar   = (float*)sym(g_Ar);
    int*    tix  = (int*)sym(g_tidx);
    float*  tw   = (float*)sym(g_tw);
    float*  rst  = (float*)sym(g_rst);
    float*  y    = (float*)sym(g_y);
    float*  hid  = (float*)sym(g_hid);

    // attention-vector folding (kills the fh/ftl GEMMs entirely)
    reduce_attn_kernel<<<8, 256>>>(W_head, attn_h, Ah);   // launch 0
    reduce_attn_kernel<<<8, 256>>>(W_tail, attn_t, At);   // launch 1
    reduce_attn_kernel<<<8, 256>>>(W_rel,  attn_r, Ar);   // launch 2

    // layer norms
    ln_kernel<false><<<NN, 256>>>(ent, nullptr, ln_ent_g, ln_ent_b, x, nullptr, NN);   // 3
    ln_kernel<false><<<RR, 256>>>(rel, nullptr, ln_rel_g, ln_rel_b, rln, nullptr, RR); // 4

    // feat0 = x @ W_ent (tensor cores, tf32) — launch 5 so ncu -s 5 captures it
    {
        dim3 grid(FF / 128, (NN + 127) / 128);
        tf32_gemm<false, false, false><<<grid, 256>>>(x, W_ent, nullptr, nullptr, fe, NN, FF, FF);
    }

    // cast feat0 to fp16 for the diffusion path
    cast_kernel<<<(NN * FF + 1023) / 1024, 1024>>>(fe, fe16, NN * FF);

    // logits
    dot_heads_kernel<<<NN, 256>>>(x, Ah, At, eh, et, NN);
    dot_heads_kernel<<<RR, 256>>>(rln, Ar, Ar, er, er, RR);

    // edge softmax + top-k -> compacted sparse attention
    attn_topk_kernel<<<(NN * 32 + 255) / 256, 256>>>(eh, et, er, src, rid, tix, tw);

    // 10 PPR hops (ping-pong, fp16 storage)
    for (int it = 0; it < HOPS; it++) {
        const __half* fin = (it == 0) ? fe16 : ((it & 1) ? fA16 : fB16);
        __half* fout = (it & 1) ? fB16 : fA16;
        hop_kernel<<<NN, 256>>>(fin, fout, fe16, tix, tw);
    }
    // final feat in fB16 (last it = 9, odd -> fB16)

    // residual + LN (fp16 feat input + fp32 residual)
    ln_kernel<true><<<NN, 256>>>(fB16, ent, ln_ff_g, ln_ff_b, y, rst, NN);

    // FFN (tensor cores, tf32)
    {
        dim3 grid1(FHID / 128, (NN + 127) / 128);
        tf32_gemm<true, true, false><<<grid1, 256>>>(y, ffn_W1, ffn_b1, nullptr, hid, NN, FF, FHID);
        dim3 grid2(FF / 128, (NN + 127) / 128);
        tf32_gemm<true, false, true><<<grid2, 256>>>(hid, ffn_W2, ffn_b2, rst, out, NN, FHID, FF);
    }
}